// round 12
// baseline (speedup 1.0000x reference)
#include <cuda_runtime.h>
#include <cstdint>

// Problem dims
#define NB 128   // batch (GEMM M)
#define NI 256   // in_features (GEMM K)
#define NH 128   // H (grid)
#define NO 32    // OUT (GEMM N)

#define DROW 260  // padded row stride in 32-bit words (conflict-free)

// Accumulators: {sum_h w, sum_h w*eta} per (b,o). Zero at module load;
// re-zeroed by the tail CTA after each launch -> clean for every replay.
__device__ float2 g_acc[NB * NO];
__device__ unsigned int g_done = 0;

// RNA round-to-tf32 as a bit trick: HMMA truncates the low 13 mantissa bits
// of its f32 operands, so adding half-ulp (0x1000) first == cvt.rna.tf32.
// All our values are >= 0, so half-away == RNA. One IADD replaces one CVT.
static __device__ __forceinline__ uint32_t tf32_rna_bits(float f) {
    return __float_as_uint(f) + 0x1000u;
}

static __device__ __forceinline__ void mma_tf32(
    float d[4], uint32_t a0, uint32_t a1, uint32_t a2, uint32_t a3,
    uint32_t b0, uint32_t b1)
{
    asm volatile(
        "mma.sync.aligned.m16n8k8.row.col.f32.tf32.tf32.f32 "
        "{%0,%1,%2,%3}, {%4,%5,%6,%7}, {%8,%9}, {%0,%1,%2,%3};"
        : "+f"(d[0]), "+f"(d[1]), "+f"(d[2]), "+f"(d[3])
        : "r"(a0), "r"(a1), "r"(a2), "r"(a3), "r"(b0), "r"(b1));
}

// ---------------------------------------------------------------------------
// Single kernel: ONE CTA per h (128 CTAs).
//   Part 1: HMMA TF32 GEMM (R10-proven layout), w = 1/(s+eps^2) in registers.
//   Part 2: atomicAdd {w, w*eta} into g_acc[b][o]  (fire-and-forget REDG).
//   Tail:   LAST-arriving CTA computes the 4096 outputs, re-zeroes g_acc.
//   No grid barrier: nobody spins; non-last CTAs exit immediately.
// ---------------------------------------------------------------------------
__global__ __launch_bounds__(512, 1) void order1_one(
    const float* __restrict__ input,      // [NB][NI]
    const float* __restrict__ sigma_psi,  // [NI][NH][NO]
    const float* __restrict__ chi,        // [NI][NH]
    const float* __restrict__ sigma_eps,  // [NH][NO]
    const float* __restrict__ eta,        // [NH][NO]
    const float* __restrict__ mu_phi,     // [NO]
    const float* __restrict__ sigma_phi,  // [NO]
    float* __restrict__ out, int out_size)
{
    extern __shared__ uint32_t usmem[];
    uint32_t* As = usmem;               // [NB][DROW] tf32 bits
    uint32_t* Bs = usmem + NB * DROW;   // [NO][DROW] tf32 bits

    const int h    = blockIdx.x;
    const int tid  = threadIdx.x;
    const int wid  = tid >> 5;
    const int lane = tid & 31;

    // ---- Phase 1: Bs[o][i] = tf32(sigma_psi[i,h,o]^2) ----
    {
        const float4* sp4 = reinterpret_cast<const float4*>(sigma_psi);
#pragma unroll
        for (int k = 0; k < 4; k++) {
            int idx4 = tid + k * 512;          // 0..2047
            int i  = idx4 >> 3;
            int o4 = idx4 & 7;
            float4 v = sp4[(i * NH + h) * 8 + o4];
            Bs[(o4 * 4 + 0) * DROW + i] = tf32_rna_bits(v.x * v.x);
            Bs[(o4 * 4 + 1) * DROW + i] = tf32_rna_bits(v.y * v.y);
            Bs[(o4 * 4 + 2) * DROW + i] = tf32_rna_bits(v.z * v.z);
            Bs[(o4 * 4 + 3) * DROW + i] = tf32_rna_bits(v.w * v.w);
        }
    }

    // ---- Phase 2: As[b][i] = tf32((chi[i,h]-x[b,i])^2), STS.128 ----
    {
        const int iq = tid & 63;   // i-quad
        const int bb = tid >> 6;   // 0..7 (uniform within warp)
        const int i  = iq * 4;
        const float c0 = chi[(i + 0) * NH + h];
        const float c1 = chi[(i + 1) * NH + h];
        const float c2 = chi[(i + 2) * NH + h];
        const float c3 = chi[(i + 3) * NH + h];
#pragma unroll 4
        for (int k = 0; k < 16; k++) {
            const int b = bb + 8 * k;
            float4 x4 = *reinterpret_cast<const float4*>(input + b * NI + i);
            float d0 = c0 - x4.x, d1 = c1 - x4.y, d2 = c2 - x4.z, d3 = c3 - x4.w;
            uint4 u;
            u.x = tf32_rna_bits(d0 * d0);
            u.y = tf32_rna_bits(d1 * d1);
            u.z = tf32_rna_bits(d2 * d2);
            u.w = tf32_rna_bits(d3 * d3);
            *reinterpret_cast<uint4*>(As + b * DROW + i) = u;
        }
    }
    __syncthreads();

    // ---- MMA: 16 warps = 8 M-tiles x 2 N-halves, 32 K-steps of 8 ----
    {
        const int m  = wid >> 1;
        const int nh = wid & 1;
        const int g  = lane >> 2;
        const int c  = lane & 3;

        const uint32_t* pA0 = As + (m * 16 + g) * DROW + c;
        const uint32_t* pA1 = pA0 + 8 * DROW;
        const uint32_t* pB0 = Bs + (nh * 16 + g) * DROW + c;
        const uint32_t* pB1 = pB0 + 8 * DROW;

        float acc0[4] = {0.f, 0.f, 0.f, 0.f};
        float acc1[4] = {0.f, 0.f, 0.f, 0.f};

#pragma unroll 8
        for (int t = 0; t < 32; t++) {
            const int koff = t * 8;
            uint32_t a0 = pA0[koff];
            uint32_t a1 = pA1[koff];
            uint32_t a2 = pA0[koff + 4];
            uint32_t a3 = pA1[koff + 4];
            uint32_t b00 = pB0[koff];
            uint32_t b01 = pB0[koff + 4];
            uint32_t b10 = pB1[koff];
            uint32_t b11 = pB1[koff + 4];
            mma_tf32(acc0, a0, a1, a2, a3, b00, b01);
            mma_tf32(acc1, a0, a1, a2, a3, b10, b11);
        }

        // ---- Epilogue: w = 1/(s+eps^2); REDG {w, w*eta} into g_acc ----
        const int r0 = m * 16 + g;
        const int r1 = r0 + 8;
        const int o0 = nh * 16 + c * 2;
        const int o1 = o0 + 8;

        const float* se = sigma_eps + h * NO;
        const float* et = eta + h * NO;
        float e00 = se[o0], e01 = se[o0 + 1], e10 = se[o1], e11 = se[o1 + 1];
        float t00 = et[o0], t01 = et[o0 + 1], t10 = et[o1], t11 = et[o1 + 1];
        e00 *= e00; e01 *= e01; e10 *= e10; e11 *= e11;

        float w00 = __fdividef(1.f, acc0[0] + e00);   // (r0, o0)
        float w01 = __fdividef(1.f, acc0[1] + e01);   // (r0, o0+1)
        float w02 = __fdividef(1.f, acc0[2] + e00);   // (r1, o0)
        float w03 = __fdividef(1.f, acc0[3] + e01);   // (r1, o0+1)
        float w10 = __fdividef(1.f, acc1[0] + e10);   // (r0, o1)
        float w11 = __fdividef(1.f, acc1[1] + e11);   // (r0, o1+1)
        float w12 = __fdividef(1.f, acc1[2] + e10);   // (r1, o1)
        float w13 = __fdividef(1.f, acc1[3] + e11);   // (r1, o1+1)

        float* a00 = &g_acc[r0 * NO + o0].x;
        float* a01 = &g_acc[r0 * NO + o0 + 1].x;
        float* a02 = &g_acc[r1 * NO + o0].x;
        float* a03 = &g_acc[r1 * NO + o0 + 1].x;
        float* a10 = &g_acc[r0 * NO + o1].x;
        float* a11 = &g_acc[r0 * NO + o1 + 1].x;
        float* a12 = &g_acc[r1 * NO + o1].x;
        float* a13 = &g_acc[r1 * NO + o1 + 1].x;

        atomicAdd(a00,     w00); atomicAdd(a00 + 1, w00 * t00);
        atomicAdd(a01,     w01); atomicAdd(a01 + 1, w01 * t01);
        atomicAdd(a02,     w02); atomicAdd(a02 + 1, w02 * t00);
        atomicAdd(a03,     w03); atomicAdd(a03 + 1, w03 * t01);
        atomicAdd(a10,     w10); atomicAdd(a10 + 1, w10 * t10);
        atomicAdd(a11,     w11); atomicAdd(a11 + 1, w11 * t11);
        atomicAdd(a12,     w12); atomicAdd(a12 + 1, w12 * t10);
        atomicAdd(a13,     w13); atomicAdd(a13 + 1, w13 * t11);
    }

    // ---- Arrival: last CTA (nobody waits) does the 4096-element tail ----
    __threadfence();     // release our REDG updates
    __syncthreads();
    __shared__ int s_last;
    if (tid == 0)
        s_last = (atomicAdd(&g_done, 1u) == (unsigned)NH - 1u);
    __syncthreads();
    if (!s_last) return;

    __threadfence();     // acquire: all other CTAs' REDGs now visible via L2

    {
        // thread t: b = t/4, o = (t%4)*8 .. +7  (8 (b,o) pairs = 4 float4)
        const int b  = tid >> 2;
        const int os = (tid & 3) * 8;
        const float4* gp =
            reinterpret_cast<const float4*>(g_acc) + (b * NO + os) / 2 / 1 * 1; // index below
        const float4* gbase =
            reinterpret_cast<const float4*>(g_acc) + ((b * NO + os) >> 1);

        float pm[8], ps[8];
#pragma unroll
        for (int j = 0; j < 4; j++) {
            float4 f = __ldcg(gbase + j);          // {sw0, swe0, sw1, swe1}
            const int o = os + 2 * j;
            float sp0 = sigma_phi[o],     mp0 = mu_phi[o];
            float sp1 = sigma_phi[o + 1], mp1 = mu_phi[o + 1];
            float sq0 = sp0 * sp0, sq1 = sp1 * sp1;
            float inv0 = __fdividef(1.f, fmaf(sq0, f.x, 1.f));
            float inv1 = __fdividef(1.f, fmaf(sq1, f.z, 1.f));
            pm[2 * j]     = (mp0 + sq0 * f.y) * inv0;
            pm[2 * j + 1] = (mp1 + sq1 * f.w) * inv1;
            ps[2 * j]     = sq0 * inv0;
            ps[2 * j + 1] = sq1 * inv1;
        }
        (void)gp;
        *reinterpret_cast<float4*>(out + b * NO + os) =
            make_float4(pm[0], pm[1], pm[2], pm[3]);
        *reinterpret_cast<float4*>(out + b * NO + os + 4) =
            make_float4(pm[4], pm[5], pm[6], pm[7]);
        if (out_size >= 2 * NB * NO) {
            *reinterpret_cast<float4*>(out + NB * NO + b * NO + os) =
                make_float4(ps[0], ps[1], ps[2], ps[3]);
            *reinterpret_cast<float4*>(out + NB * NO + b * NO + os + 4) =
                make_float4(ps[4], ps[5], ps[6], ps[7]);
        }

        // Re-zero accumulators for the next graph replay
        float4* gz = reinterpret_cast<float4*>(g_acc) + ((b * NO + os) >> 1);
        float4 z = make_float4(0.f, 0.f, 0.f, 0.f);
#pragma unroll
        for (int j = 0; j < 4; j++) gz[j] = z;
    }
    __syncthreads();
    if (tid == 0) {
        g_done = 0u;
        __threadfence();
    }
}

extern "C" void kernel_launch(void* const* d_in, const int* in_sizes, int n_in,
                              void* d_out, int out_size) {
    const float* input     = (const float*)d_in[0];
    const float* sigma_psi = (const float*)d_in[1];
    const float* chi       = (const float*)d_in[2];
    const float* sigma_eps = (const float*)d_in[3];
    const float* eta       = (const float*)d_in[4];
    const float* mu_phi    = (const float*)d_in[5];
    const float* sigma_phi = (const float*)d_in[6];

    const int smemA = (NB + NO) * DROW * (int)sizeof(uint32_t);  // 166400 B
    cudaFuncSetAttribute(order1_one,
                         cudaFuncAttributeMaxDynamicSharedMemorySize, smemA);

    order1_one<<<NH, 512, smemA>>>(input, sigma_psi, chi, sigma_eps,
                                   eta, mu_phi, sigma_phi,
                                   (float*)d_out, out_size);
}

// round 13
// speedup vs baseline: 1.7506x; 1.7506x over previous
#include <cuda_runtime.h>
#include <cstdint>

// Problem dims
#define NB 128   // batch (GEMM M)
#define NI 256   // in_features (GEMM K)
#define NH 128   // H (grid)
#define NO 32    // OUT (GEMM N)

// Permuted-K smem layout: col(i) = (i&3)*68 + (i>>2); row stride 272 words.
// -> per MMA lane, fragment elements for 2 consecutive K-steps are one uint4.
// Bank check (row r, lane (g,c), col c*68 + 4*t2): bank0 = (16g + 4c) mod 32
//   phase lanes {g,g+1}x{c} -> {0,4,...,28}: conflict-free LDS.128.
#define AROW 272
#define BROW 272

// Scratch: w[b][h][o]  (fully overwritten every launch -> no init needed)
__device__ float g_w[NB * NH * NO];

// RNA round-to-tf32 bit trick (R12-validated): HMMA truncates low 13 mantissa
// bits; values are >= 0 so +0x1000 == cvt.rna.tf32. One IADD replaces one CVT.
static __device__ __forceinline__ uint32_t tf32_rna_bits(float f) {
    return __float_as_uint(f) + 0x1000u;
}

static __device__ __forceinline__ void mma_tf32(
    float d[4], uint32_t a0, uint32_t a1, uint32_t a2, uint32_t a3,
    uint32_t b0, uint32_t b1)
{
    asm volatile(
        "mma.sync.aligned.m16n8k8.row.col.f32.tf32.tf32.f32 "
        "{%0,%1,%2,%3}, {%4,%5,%6,%7}, {%8,%9}, {%0,%1,%2,%3};"
        : "+f"(d[0]), "+f"(d[1]), "+f"(d[2]), "+f"(d[3])
        : "r"(a0), "r"(a1), "r"(a2), "r"(a3), "r"(b0), "r"(b1));
}

// ---------------------------------------------------------------------------
// Kernel A: ONE CTA per h, 512 threads. HMMA TF32 GEMM with permuted-K smem:
//   D[b,o] = sum_i (chi-x)^2 * sigma_psi^2;  g_w[b][h][o] = 1/(D + eps^2)
// 16 warps = 8 M-tiles x 2 N-halves; 16 pair-steps; 4 LDS.128 + 4 HMMA each.
// ---------------------------------------------------------------------------
__global__ __launch_bounds__(512, 1) void order1_main(
    const float* __restrict__ input,      // [NB][NI]
    const float* __restrict__ sigma_psi,  // [NI][NH][NO]
    const float* __restrict__ chi,        // [NI][NH]
    const float* __restrict__ sigma_eps)  // [NH][NO]
{
    extern __shared__ uint32_t usmem[];
    uint32_t* As = usmem;               // [NB][AROW] tf32 bits, permuted-K
    uint32_t* Bs = usmem + NB * AROW;   // [NO][BROW] tf32 bits, permuted-K

    const int h    = blockIdx.x;
    const int tid  = threadIdx.x;
    const int wid  = tid >> 5;
    const int lane = tid & 31;

    // ---- Phase 1: Bs[o][perm(i)] = tf32(sigma_psi[i,h,o]^2) ----
    {
        const float4* sp4 = reinterpret_cast<const float4*>(sigma_psi);
#pragma unroll
        for (int k = 0; k < 4; k++) {
            int idx4 = tid + k * 512;          // 0..2047
            int i  = idx4 >> 3;
            int o4 = idx4 & 7;
            float4 v = sp4[(i * NH + h) * 8 + o4];
            const int pc = (i & 3) * 68 + (i >> 2);   // permuted column
            Bs[(o4 * 4 + 0) * BROW + pc] = tf32_rna_bits(v.x * v.x);
            Bs[(o4 * 4 + 1) * BROW + pc] = tf32_rna_bits(v.y * v.y);
            Bs[(o4 * 4 + 2) * BROW + pc] = tf32_rna_bits(v.z * v.z);
            Bs[(o4 * 4 + 3) * BROW + pc] = tf32_rna_bits(v.w * v.w);
        }
    }

    // ---- Phase 2: As[b][perm(i)] = tf32((chi[i,h]-x[b,i])^2) ----
    {
        const int iq = tid & 63;   // i-quad: i = 4*iq + j
        const int bb = tid >> 6;   // 0..7 (uniform within warp)
        const int i  = iq * 4;
        const float c0 = chi[(i + 0) * NH + h];
        const float c1 = chi[(i + 1) * NH + h];
        const float c2 = chi[(i + 2) * NH + h];
        const float c3 = chi[(i + 3) * NH + h];
#pragma unroll 4
        for (int k = 0; k < 16; k++) {
            const int b = bb + 8 * k;
            float4 x4 = *reinterpret_cast<const float4*>(input + b * NI + i);
            float d0 = c0 - x4.x, d1 = c1 - x4.y, d2 = c2 - x4.z, d3 = c3 - x4.w;
            uint32_t* row = As + b * AROW + iq;   // perm(4iq+j) = j*68 + iq
            row[0 * 68] = tf32_rna_bits(d0 * d0);
            row[1 * 68] = tf32_rna_bits(d1 * d1);
            row[2 * 68] = tf32_rna_bits(d2 * d2);
            row[3 * 68] = tf32_rna_bits(d3 * d3);
        }
    }
    __syncthreads();

    // ---- MMA: 16 pair-steps; per pair-step 4x LDS.128 + 4x HMMA ----
    {
        const int m  = wid >> 1;
        const int nh = wid & 1;
        const int g  = lane >> 2;
        const int c  = lane & 3;

        const uint32_t* pa0 = As + (m * 16 + g) * AROW + c * 68;
        const uint32_t* pa1 = pa0 + 8 * AROW;
        const uint32_t* pb0 = Bs + (nh * 16 + g) * BROW + c * 68;
        const uint32_t* pb1 = pb0 + 8 * BROW;

        float acc0[4] = {0.f, 0.f, 0.f, 0.f};
        float acc1[4] = {0.f, 0.f, 0.f, 0.f};

#pragma unroll
        for (int t2 = 0; t2 < 16; t2++) {
            const int off = 4 * t2;
            // {a0(t), a2(t), a0(t+1), a2(t+1)} etc., t = 2*t2
            uint4 la0 = *reinterpret_cast<const uint4*>(pa0 + off);
            uint4 la1 = *reinterpret_cast<const uint4*>(pa1 + off);
            uint4 lb0 = *reinterpret_cast<const uint4*>(pb0 + off);
            uint4 lb1 = *reinterpret_cast<const uint4*>(pb1 + off);
            mma_tf32(acc0, la0.x, la1.x, la0.y, la1.y, lb0.x, lb0.y);
            mma_tf32(acc1, la0.x, la1.x, la0.y, la1.y, lb1.x, lb1.y);
            mma_tf32(acc0, la0.z, la1.z, la0.w, la1.w, lb0.z, lb0.w);
            mma_tf32(acc1, la0.z, la1.z, la0.w, la1.w, lb1.z, lb1.w);
        }

        // ---- Epilogue (R10-proven fragment map): w = 1/(s+eps^2) ----
        const int r0 = m * 16 + g;
        const int r1 = r0 + 8;
        const int o0 = nh * 16 + c * 2;
        const int o1 = o0 + 8;

        const float* se = sigma_eps + h * NO;
        float e00 = se[o0], e01 = se[o0 + 1], e10 = se[o1], e11 = se[o1 + 1];
        e00 *= e00; e01 *= e01; e10 *= e10; e11 *= e11;

        float* g0 = g_w + (r0 * NH + h) * NO;
        float* g1 = g_w + (r1 * NH + h) * NO;

        *reinterpret_cast<float2*>(g0 + o0) =
            make_float2(__fdividef(1.f, acc0[0] + e00),
                        __fdividef(1.f, acc0[1] + e01));
        *reinterpret_cast<float2*>(g1 + o0) =
            make_float2(__fdividef(1.f, acc0[2] + e00),
                        __fdividef(1.f, acc0[3] + e01));
        *reinterpret_cast<float2*>(g0 + o1) =
            make_float2(__fdividef(1.f, acc1[0] + e10),
                        __fdividef(1.f, acc1[1] + e11));
        *reinterpret_cast<float2*>(g1 + o1) =
            make_float2(__fdividef(1.f, acc1[2] + e10),
                        __fdividef(1.f, acc1[3] + e11));
    }
}

// ---------------------------------------------------------------------------
// Kernel B: CTA per b, 512 threads (R8-proven verbatim).
// ---------------------------------------------------------------------------
__global__ __launch_bounds__(512) void order1_finish(
    const float* __restrict__ eta,        // [NH][NO]
    const float* __restrict__ mu_phi,     // [NO]
    const float* __restrict__ sigma_phi,  // [NO]
    float* __restrict__ out, int out_size)
{
    __shared__ float4 sA[16 * 8];
    __shared__ float4 sB[16 * 8];

    const int b = blockIdx.x;
    const int t = threadIdx.x;
    const int wid = t >> 5;
    const int l = t & 31;

    const float4* row4 = reinterpret_cast<const float4*>(g_w + b * NH * NO);
    const float4* eta4 = reinterpret_cast<const float4*>(eta);

    float4 sw  = make_float4(0.f, 0.f, 0.f, 0.f);
    float4 swe = make_float4(0.f, 0.f, 0.f, 0.f);
#pragma unroll
    for (int rep = 0; rep < 2; rep++) {
        int idx = t + rep * 512;
        float4 w4 = row4[idx];
        float4 e4 = eta4[idx];
        sw.x += w4.x; sw.y += w4.y; sw.z += w4.z; sw.w += w4.w;
        swe.x += w4.x * e4.x; swe.y += w4.y * e4.y;
        swe.z += w4.z * e4.z; swe.w += w4.w * e4.w;
    }

#pragma unroll
    for (int m = 8; m <= 16; m <<= 1) {
        sw.x += __shfl_xor_sync(0xffffffffu, sw.x, m);
        sw.y += __shfl_xor_sync(0xffffffffu, sw.y, m);
        sw.z += __shfl_xor_sync(0xffffffffu, sw.z, m);
        sw.w += __shfl_xor_sync(0xffffffffu, sw.w, m);
        swe.x += __shfl_xor_sync(0xffffffffu, swe.x, m);
        swe.y += __shfl_xor_sync(0xffffffffu, swe.y, m);
        swe.z += __shfl_xor_sync(0xffffffffu, swe.z, m);
        swe.w += __shfl_xor_sync(0xffffffffu, swe.w, m);
    }
    if (l < 8) {
        sA[wid * 8 + l] = sw;
        sB[wid * 8 + l] = swe;
    }
    __syncthreads();

    if (t < 8) {
        float4 a = sA[t], bb = sB[t];
#pragma unroll
        for (int k = 1; k < 16; k++) {
            float4 a2 = sA[k * 8 + t], b2 = sB[k * 8 + t];
            a.x += a2.x; a.y += a2.y; a.z += a2.z; a.w += a2.w;
            bb.x += b2.x; bb.y += b2.y; bb.z += b2.z; bb.w += b2.w;
        }
        const int o = t * 4;
        float4 mp = *reinterpret_cast<const float4*>(mu_phi + o);
        float4 sp = *reinterpret_cast<const float4*>(sigma_phi + o);
        float swa[4]  = {a.x, a.y, a.z, a.w};
        float swea[4] = {bb.x, bb.y, bb.z, bb.w};
        float mpa[4]  = {mp.x, mp.y, mp.z, mp.w};
        float spa[4]  = {sp.x, sp.y, sp.z, sp.w};
        float pm[4], ps[4];
#pragma unroll
        for (int cc = 0; cc < 4; cc++) {
            float sp2 = spa[cc] * spa[cc];
            float inv = __fdividef(1.0f, fmaf(sp2, swa[cc], 1.0f));
            pm[cc] = (mpa[cc] + sp2 * swea[cc]) * inv;
            ps[cc] = sp2 * inv;
        }
        *reinterpret_cast<float4*>(out + b * NO + o) =
            make_float4(pm[0], pm[1], pm[2], pm[3]);
        if (out_size >= 2 * NB * NO)
            *reinterpret_cast<float4*>(out + NB * NO + b * NO + o) =
                make_float4(ps[0], ps[1], ps[2], ps[3]);
    }
}

extern "C" void kernel_launch(void* const* d_in, const int* in_sizes, int n_in,
                              void* d_out, int out_size) {
    const float* input     = (const float*)d_in[0];
    const float* sigma_psi = (const float*)d_in[1];
    const float* chi       = (const float*)d_in[2];
    const float* sigma_eps = (const float*)d_in[3];
    const float* eta       = (const float*)d_in[4];
    const float* mu_phi    = (const float*)d_in[5];
    const float* sigma_phi = (const float*)d_in[6];

    const int smemA = (NB * AROW + NO * BROW) * (int)sizeof(uint32_t); // 174080
    cudaFuncSetAttribute(order1_main,
                         cudaFuncAttributeMaxDynamicSharedMemorySize, smemA);

    order1_main<<<NH, 512, smemA>>>(input, sigma_psi, chi, sigma_eps);
    order1_finish<<<NB, 512>>>(eta, mu_phi, sigma_phi, (float*)d_out, out_size);
}